// round 1
// baseline (speedup 1.0000x reference)
#include <cuda_runtime.h>

// LatticeQuantizer: hierarchical nested E8 lattice quantize (M=3, Q=4).
// One thread per row of 8 floats; everything in registers, fully unrolled.
// G / G_inv structure is hardcoded analytically (exact dyadic arithmetic,
// bit-identical to the reference's dense fp32 matvecs).

#define TINY_F 1.1920928955078125e-07f  // np.finfo(float32).eps

static __device__ __forceinline__ float cround(float x) {
    // floor(x - sign(x)*tiny + 0.5); copysign(tiny, +/-0) is harmless here.
    float s = copysignf(TINY_F, x);
    return floorf((x - s) + 0.5f);
}

// closest point in E8 = D8 U (D8 + 1/2), faithful to the reference's
// tie-breaking (first argmax, custom_round semantics, strict d0<d1).
static __device__ __forceinline__ void cp_e8(const float x[8], float out[8]) {
    // ---- candidate A: round each coord (D8 branch) ----
    float fA[8], rA[8], sA = 0.f;
#pragma unroll
    for (int i = 0; i < 8; i++) {
        fA[i] = cround(x[i]);
        rA[i] = x[i] - fA[i];
        sA += fA[i];
    }
    bool oddA = (((int)sA) & 1) != 0;
    float mA = fabsf(rA[0]); float rkA = rA[0], xkA = x[0]; int kA = 0;
#pragma unroll
    for (int i = 1; i < 8; i++) {
        float d = fabsf(rA[i]);
        bool gt = d > mA;                 // strict: keep FIRST max (argmax)
        mA  = gt ? d     : mA;
        rkA = gt ? rA[i] : rkA;
        xkA = gt ? x[i]  : xkA;
        kA  = gt ? i     : kA;
    }
    // step: r>0 -> +1 ; r<0 -> -1 ; r==0 -> (x>=0 ? -1 : +1)
    float stepA = (rkA > 0.f) ? 1.f : ((rkA < 0.f) ? -1.f : ((xkA >= 0.f) ? -1.f : 1.f));

    // ---- candidate B: round(x - 1/2) + 1/2 ----
    float fB[8], rB[8], sB = 0.f;
#pragma unroll
    for (int i = 0; i < 8; i++) {
        float xs = x[i] - 0.5f;
        fB[i] = cround(xs);
        rB[i] = xs - fB[i];
        sB += fB[i];
    }
    bool oddB = (((int)sB) & 1) != 0;
    float mB = fabsf(rB[0]); float rkB = rB[0], xkB = x[0] - 0.5f; int kB = 0;
#pragma unroll
    for (int i = 1; i < 8; i++) {
        float d = fabsf(rB[i]);
        bool gt = d > mB;
        mB  = gt ? d            : mB;
        rkB = gt ? rB[i]        : rkB;
        xkB = gt ? (x[i] - 0.5f): xkB;
        kB  = gt ? i            : kB;
    }
    float stepB = (rkB > 0.f) ? 1.f : ((rkB < 0.f) ? -1.f : ((xkB >= 0.f) ? -1.f : 1.f));

    // ---- materialize candidates + distances (mul/add kept separate to
    //      avoid FMA contraction so fp matches XLA's mul-then-reduce) ----
    float d0 = 0.f, d1 = 0.f;
    float yA[8], yB[8];
#pragma unroll
    for (int i = 0; i < 8; i++) {
        float addA = (oddA && (i == kA)) ? stepA : 0.f;
        float addB = (oddB && (i == kB)) ? stepB : 0.f;
        yA[i] = fA[i] + addA;                 // exact (integers)
        yB[i] = (fB[i] + addB) + 0.5f;        // exact (half-integers)
        float ra = x[i] - yA[i];
        float rb = x[i] - yB[i];
        d0 = __fadd_rn(d0, __fmul_rn(ra, ra));
        d1 = __fadd_rn(d1, __fmul_rn(rb, rb));
    }
    bool pick0 = d0 < d1;
#pragma unroll
    for (int i = 0; i < 8; i++) out[i] = pick0 ? yA[i] : yB[i];
}

__global__ void __launch_bounds__(256)
lq_kernel(const float4* __restrict__ xin,
          const float* __restrict__ betap,
          const float* __restrict__ epsp,
          float4* __restrict__ outp,
          int nrows)
{
    int row = blockIdx.x * blockDim.x + threadIdx.x;
    if (row >= nrows) return;

    float beta = __ldg(betap);
    float eps[8];
#pragma unroll
    for (int i = 0; i < 8; i++) eps[i] = __ldg(epsp + i);

    float4 a = __ldg(xin + 2 * row);
    float4 c4 = __ldg(xin + 2 * row + 1);
    float x[8] = {a.x, a.y, a.z, a.w, c4.x, c4.y, c4.z, c4.w};

    // ---- encode ----
    float xl[8];
#pragma unroll
    for (int i = 0; i < 8; i++) xl[i] = x[i] / beta;   // IEEE divide (beta=1 exact)

    float bm[3][8];
#pragma unroll
    for (int m = 0; m < 3; m++) {
        float t[8];
#pragma unroll
        for (int i = 0; i < 8; i++) t[i] = xl[i] + eps[i];
        float cp[8];
        cp_e8(t, cp);

        // z = cp @ G_inv  (analytic forward-solve of rows[j] . z = cp_j;
        // all values dyadic -> exact, identical to dense fp32 matvec)
        float z[8];
        z[0] = 0.5f * cp[0];
        float sum06 = z[0];
#pragma unroll
        for (int i = 1; i < 7; i++) { z[i] = cp[i] + z[i - 1]; sum06 += z[i]; }
        z[7] = 2.f * cp[7] - sum06;

        // b = custom_round(fmod(z, 4))  — fmod via exact z - 4*trunc(z/4)
#pragma unroll
        for (int i = 0; i < 8; i++) {
            float q = truncf(z[i] * 0.25f);
            float r = __fmaf_rn(-4.f, q, z[i]);   // exact (dyadic)
            bm[m][i] = cround(r);
        }
#pragma unroll
        for (int i = 0; i < 8; i++) xl[i] = cp[i] * 0.25f;   // /Q exact
    }

    // ---- decode ----
    float xh[8] = {0.f, 0.f, 0.f, 0.f, 0.f, 0.f, 0.f, 0.f};
    float scale = 1.f;
#pragma unroll
    for (int m = 0; m < 3; m++) {
        const float* b = bm[m];
        // Gb = b @ G.T  (sparse structure of E8 generator rows; exact)
        float h = 0.5f * b[7];
        float g[8];
        g[0] = 2.f * b[0] - b[1] + h;
#pragma unroll
        for (int j = 1; j < 6; j++) g[j] = b[j] - b[j + 1] + h;
        g[6] = b[6] + h;
        g[7] = h;

        float gq[8];
#pragma unroll
        for (int i = 0; i < 8; i++) gq[i] = g[i] * 0.25f;    // /Q exact (eighths)
        float cp2[8];
        cp_e8(gq, cp2);

#pragma unroll
        for (int i = 0; i < 8; i++) {
            float xi = g[i] - 4.f * cp2[i];    // exact dyadic
            xh[i] += scale * xi;               // exact dyadic accumulation
        }
        scale *= 4.f;
    }

    float4 o0, o1;
    o0.x = beta * xh[0]; o0.y = beta * xh[1]; o0.z = beta * xh[2]; o0.w = beta * xh[3];
    o1.x = beta * xh[4]; o1.y = beta * xh[5]; o1.z = beta * xh[6]; o1.w = beta * xh[7];
    outp[2 * row]     = o0;
    outp[2 * row + 1] = o1;
}

extern "C" void kernel_launch(void* const* d_in, const int* in_sizes, int n_in,
                              void* d_out, int out_size)
{
    const float* x = (const float*)d_in[0];
    // locate beta (1 elem) and eps (8 elems) robustly by size; G/G_inv (64) unused
    const float* beta = nullptr;
    const float* eps  = nullptr;
    for (int i = 1; i < n_in; i++) {
        if (in_sizes[i] == 1) beta = (const float*)d_in[i];
        else if (in_sizes[i] == 8) eps = (const float*)d_in[i];
    }
    int nrows = in_sizes[0] / 8;
    int threads = 256;
    int blocks = (nrows + threads - 1) / threads;
    lq_kernel<<<blocks, threads>>>((const float4*)x, beta, eps, (float4*)d_out, nrows);
}

// round 8
// speedup vs baseline: 1.0845x; 1.0845x over previous
#include <cuda_runtime.h>

// LatticeQuantizer: hierarchical nested E8 lattice quantize (M=3, Q=4).
// HARD-WON RULE: xs = fl(x - 0.5) is INEXACT for |x| < 0.5, so B-candidate
// residuals/outputs must be computed from x and y=(fB+step)+0.5 directly
// (reference order) in the encode path. In decode, inputs are exact eighths
// -> xs is exact -> residual forms are bit-identical and allowed.
// A-branch residuals (x - cround(x)) are exact for ALL inputs.

#define TINY_F 1.1920928955078125e-07f  // np.finfo(float32).eps

static __device__ __forceinline__ float cround(float x) {
    float s = copysignf(TINY_F, x);
    return floorf((x - s) + 0.5f);
}

// closest point in E8 = D8 U (D8 + 1/2), faithful tie-breaking.
// EXACT=true only when x lanes are exact dyadic eighths (decode path).
template<bool EXACT>
static __device__ __forceinline__ void cp_e8(const float x[8], float out[8]) {
    // ---- candidate A (residual form; exact for all inputs) ----
    float rA[8]; float sA = 0.f;
#pragma unroll
    for (int i = 0; i < 8; i++) {
        float f = cround(x[i]);
        rA[i] = x[i] - f;          // exact: representable on x's grid
        sA += f;                   // exact (small ints)
    }
    float rkA = rA[0], xkA = x[0]; int kA = 0;
#pragma unroll
    for (int i = 1; i < 8; i++) {
        bool gt = fabsf(rA[i]) > fabsf(rkA);   // FIRST max wins (argmax)
        rkA = gt ? rA[i] : rkA;
        xkA = gt ? x[i]  : xkA;
        kA  = gt ? i     : kA;
    }
    float stepA = (rkA > 0.f) ? 1.f
                : ((rkA < 0.f) ? -1.f : ((xkA >= 0.f) ? -1.f : 1.f));
    bool oddA = (((int)sA) & 1) != 0;
    int  kAe  = oddA ? kA : 8;     // 8 = no flip
    float rcA = rkA - stepA;       // fl == fl(x_k - (fA_k + step)), rA exact

    // ---- candidate B ----
    float rB[8], fB[8]; float sB = 0.f;
#pragma unroll
    for (int i = 0; i < 8; i++) {
        float xs = x[i] - 0.5f;    // may round when |x|<0.5 (reference does same)
        float f  = cround(xs);
        fB[i] = f;
        rB[i] = xs - f;            // exact relative to xs
        sB += f;
    }
    float rkB = rB[0], xkB = x[0] - 0.5f; int kB = 0;
#pragma unroll
    for (int i = 1; i < 8; i++) {
        bool gt = fabsf(rB[i]) > fabsf(rkB);
        rkB = gt ? rB[i]         : rkB;
        xkB = gt ? (x[i] - 0.5f) : xkB;
        kB  = gt ? i             : kB;
    }
    float stepB = (rkB > 0.f) ? 1.f
                : ((rkB < 0.f) ? -1.f : ((xkB >= 0.f) ? -1.f : 1.f));
    bool oddB = (((int)sB) & 1) != 0;
    int  kBe  = oddB ? kB : 8;
    float rcB = rkB - stepB;

    float d0 = 0.f, d1 = 0.f;
    if (EXACT) {
        // xs exact here -> rB == x - (fB + 0.5) in real arithmetic ->
        // residual substitution bit-identical to reference.
#pragma unroll
        for (int i = 0; i < 8; i++) {
            float a = (i == kAe) ? rcA : rA[i];
            float b = (i == kBe) ? rcB : rB[i];
            d0 = __fadd_rn(d0, __fmul_rn(a, a));
            d1 = __fadd_rn(d1, __fmul_rn(b, b));
        }
        bool p0 = d0 < d1;
        int   ksel    = p0 ? kAe   : kBe;
        float stepsel = p0 ? stepA : stepB;
#pragma unroll
        for (int i = 0; i < 8; i++) {
            float t = x[i] - (p0 ? rA[i] : rB[i]);   // exact lattice coord
            out[i] = (i == ksel) ? (t + stepsel) : t;
        }
    } else {
        // encode: B must be materialized from x (reference order) because
        // xs may have rounded; A stays in residual form (exact).
        float yB[8];
#pragma unroll
        for (int i = 0; i < 8; i++) {
            float addB = (oddB && (i == kB)) ? stepB : 0.f;
            yB[i] = (fB[i] + addB) + 0.5f;
            float a  = (i == kAe) ? rcA : rA[i];
            float rb = x[i] - yB[i];
            d0 = __fadd_rn(d0, __fmul_rn(a, a));
            d1 = __fadd_rn(d1, __fmul_rn(rb, rb));
        }
        bool p0 = d0 < d1;
#pragma unroll
        for (int i = 0; i < 8; i++) {
            float oA = x[i] - rA[i];               // == fA exactly
            oA = (i == kAe) ? (oA + stepA) : oA;   // exact +-1 patch
            out[i] = p0 ? oA : yB[i];
        }
    }
}

__global__ void __launch_bounds__(256)
lq_kernel(const float4* __restrict__ xin,
          const float* __restrict__ betap,
          const float* __restrict__ epsp,
          float4* __restrict__ outp,
          int nrows)
{
    int row = blockIdx.x * blockDim.x + threadIdx.x;
    if (row >= nrows) return;

    float beta = __ldg(betap);
    float eps[8];
#pragma unroll
    for (int i = 0; i < 8; i++) eps[i] = __ldg(epsp + i);

    float4 a0 = __ldg(xin + 2 * row);
    float4 a1 = __ldg(xin + 2 * row + 1);
    float x[8] = {a0.x, a0.y, a0.z, a0.w, a1.x, a1.y, a1.z, a1.w};

    float xl[8];
#pragma unroll
    for (int i = 0; i < 8; i++) xl[i] = x[i] / beta;   // IEEE divide

    float xh[8] = {0.f, 0.f, 0.f, 0.f, 0.f, 0.f, 0.f, 0.f};
    float scale = 1.f;

#pragma unroll
    for (int m = 0; m < 3; m++) {
        // ---- encode layer m (R1-verbatim numerics) ----
        float t[8], cp[8];
#pragma unroll
        for (int i = 0; i < 8; i++) t[i] = xl[i] + eps[i];
        cp_e8<false>(t, cp);

        float z[8];
        z[0] = 0.5f * cp[0];
        float sum06 = z[0];
#pragma unroll
        for (int i = 1; i < 7; i++) { z[i] = cp[i] + z[i - 1]; sum06 += z[i]; }
        z[7] = 2.f * cp[7] - sum06;

        float b[8];
#pragma unroll
        for (int i = 0; i < 8; i++) {
            float q = truncf(z[i] * 0.25f);
            float r = __fmaf_rn(-4.f, q, z[i]);   // exact (dyadic)
            b[i] = cround(r);
        }
#pragma unroll
        for (int i = 0; i < 8; i++) xl[i] = cp[i] * 0.25f;

        // ---- decode layer m (R1-verbatim numerics) ----
        float h = 0.5f * b[7];
        float g[8];
        g[0] = 2.f * b[0] - b[1] + h;
#pragma unroll
        for (int j = 1; j < 6; j++) g[j] = b[j] - b[j + 1] + h;
        g[6] = b[6] + h;
        g[7] = h;

        float gq[8], cp2[8];
#pragma unroll
        for (int i = 0; i < 8; i++) gq[i] = g[i] * 0.25f;   // exact eighths
        cp_e8<true>(gq, cp2);

#pragma unroll
        for (int i = 0; i < 8; i++) {
            float xi = g[i] - 4.f * cp2[i];
            xh[i] += scale * xi;
        }
        scale *= 4.f;
    }

    float4 o0, o1;
    o0.x = beta * xh[0]; o0.y = beta * xh[1]; o0.z = beta * xh[2]; o0.w = beta * xh[3];
    o1.x = beta * xh[4]; o1.y = beta * xh[5]; o1.z = beta * xh[6]; o1.w = beta * xh[7];
    outp[2 * row]     = o0;
    outp[2 * row + 1] = o1;
}

extern "C" void kernel_launch(void* const* d_in, const int* in_sizes, int n_in,
                              void* d_out, int out_size)
{
    const float* x = (const float*)d_in[0];
    const float* beta = nullptr;
    const float* eps  = nullptr;
    for (int i = 1; i < n_in; i++) {
        if (in_sizes[i] == 1) beta = (const float*)d_in[i];
        else if (in_sizes[i] == 8) eps = (const float*)d_in[i];
    }
    int nrows = in_sizes[0] / 8;
    int threads = 256;
    int blocks = (nrows + threads - 1) / threads;
    lq_kernel<<<blocks, threads>>>((const float4*)x, beta, eps, (float4*)d_out, nrows);
}

// round 9
// speedup vs baseline: 1.2464x; 1.1493x over previous
#include <cuda_runtime.h>

// LatticeQuantizer: hierarchical nested E8 lattice quantize (M=3, Q=4).
// PROVEN RULES (7-round bisect):
//  - xs = fl(x-0.5) is INEXACT for |x|<0.5 -> encode-B candidate must be
//    materialized from x in reference order. Decode inputs are exact
//    eighths -> all residual forms / FMA / reordered exact sums are
//    bit-identical there.
//  - A-branch residuals (x - cround(x)) are exact for ALL inputs.
//  - rk==0 implies ALL residuals are zero, hence argmax k==0 -> the tie
//    step sign can be precomputed from lane 0; no per-lane xk tracking.

#define TINY_F 1.1920928955078125e-07f  // np.finfo(float32).eps

static __device__ __forceinline__ float cround(float x) {
    float s = copysignf(TINY_F, x);
    return floorf((x - s) + 0.5f);
}

// closest point in E8 = D8 U (D8 + 1/2), faithful tie-breaking.
// EXACT=true only when x lanes are exact dyadic eighths (decode path).
template<bool EXACT>
static __device__ __forceinline__ void cp_e8(const float x[8], float out[8]) {
    // ---- candidate A (residual form; exact for all inputs) ----
    float rA[8]; float sA = 0.f;
#pragma unroll
    for (int i = 0; i < 8; i++) {
        float f = cround(x[i]);
        rA[i] = x[i] - f;          // exact
        sA += f;                   // exact (small ints)
    }
    float rkA = rA[0]; int kA = 0;
#pragma unroll
    for (int i = 1; i < 8; i++) {
        bool gt = fabsf(rA[i]) > fabsf(rkA);   // FIRST max wins
        rkA = gt ? rA[i] : rkA;
        kA  = gt ? i     : kA;
    }
    // tie fallback: rk==0 => all r==0 => k==0 => xk == x[0]
    float tieA  = (x[0] >= 0.f) ? -1.f : 1.f;
    float stepA = (rkA > 0.f) ? 1.f : ((rkA < 0.f) ? -1.f : tieA);
    bool oddA = (((int)sA) & 1) != 0;
    int  kAe  = oddA ? kA : 8;     // 8 = no flip
    float rcA = rkA - stepA;       // fl == fl(x_k - (fA_k + step))

    // ---- candidate B ----
    float rB[8], fB[8]; float sB = 0.f;
#pragma unroll
    for (int i = 0; i < 8; i++) {
        float xs = x[i] - 0.5f;    // reference computes the same fl
        float f  = cround(xs);
        fB[i] = f;
        rB[i] = xs - f;            // exact relative to xs
        sB += f;
    }
    float rkB = rB[0]; int kB = 0;
#pragma unroll
    for (int i = 1; i < 8; i++) {
        bool gt = fabsf(rB[i]) > fabsf(rkB);
        rkB = gt ? rB[i] : rkB;
        kB  = gt ? i     : kB;
    }
    float tieB  = ((x[0] - 0.5f) >= 0.f) ? -1.f : 1.f;
    float stepB = (rkB > 0.f) ? 1.f : ((rkB < 0.f) ? -1.f : tieB);
    bool oddB = (((int)sB) & 1) != 0;
    int  kBe  = oddB ? kB : 8;
    float rcB = rkB - stepB;

    if (EXACT) {
        // all quantities on the 1/8 grid; squares on 1/64 grid; all sums
        // exact -> FMA + end adjustment is bit-identical to the reference
        // (bisect-proven innocent R5->R6).
        float d0 = 0.f, d1 = 0.f;
#pragma unroll
        for (int i = 0; i < 8; i++) {
            d0 = __fmaf_rn(rA[i], rA[i], d0);
            d1 = __fmaf_rn(rB[i], rB[i], d1);
        }
        float adjA = __fmul_rn(rcA, rcA) - __fmul_rn(rkA, rkA);  // exact
        float adjB = __fmul_rn(rcB, rcB) - __fmul_rn(rkB, rkB);
        d0 += oddA ? adjA : 0.f;
        d1 += oddB ? adjB : 0.f;
        bool p0 = d0 < d1;
        int   ksel    = p0 ? kAe   : kBe;
        float stepsel = p0 ? stepA : stepB;
#pragma unroll
        for (int i = 0; i < 8; i++) {
            float t = x[i] - (p0 ? rA[i] : rB[i]);   // exact lattice coord
            out[i] = (i == ksel) ? (t + stepsel) : t;
        }
    } else {
        // encode: B materialized from fB in reference order (xs may have
        // rounded); A stays in residual form (exact). [R8-proven]
        float d0 = 0.f, d1 = 0.f;
        float yB[8];
#pragma unroll
        for (int i = 0; i < 8; i++) {
            float addB = (i == kBe) ? stepB : 0.f;
            yB[i] = (fB[i] + addB) + 0.5f;
            float a  = (i == kAe) ? rcA : rA[i];
            float rb = x[i] - yB[i];
            d0 = __fadd_rn(d0, __fmul_rn(a, a));
            d1 = __fadd_rn(d1, __fmul_rn(rb, rb));
        }
        bool p0 = d0 < d1;
#pragma unroll
        for (int i = 0; i < 8; i++) {
            float addA = (i == kAe) ? stepA : 0.f;
            float oA = (x[i] - rA[i]) + addA;      // fA exact, +-1 exact
            out[i] = p0 ? oA : yB[i];
        }
    }
}

__global__ void __launch_bounds__(256)
lq_kernel(const float4* __restrict__ xin,
          const float* __restrict__ betap,
          const float* __restrict__ epsp,
          float4* __restrict__ outp,
          int nrows)
{
    int row = blockIdx.x * blockDim.x + threadIdx.x;
    if (row >= nrows) return;

    float beta = __ldg(betap);
    float eps[8];
#pragma unroll
    for (int i = 0; i < 8; i++) eps[i] = __ldg(epsp + i);

    float4 a0 = __ldg(xin + 2 * row);
    float4 a1 = __ldg(xin + 2 * row + 1);
    float x[8] = {a0.x, a0.y, a0.z, a0.w, a1.x, a1.y, a1.z, a1.w};

    // beta fast path: x/1.0 == x and 1.0*x == x bitwise (IEEE), so the
    // expensive correctly-rounded divides are skipped when beta==1.
    bool beta1 = (beta == 1.0f);
    float xl[8];
#pragma unroll
    for (int i = 0; i < 8; i++)
        xl[i] = beta1 ? x[i] : __fdiv_rn(x[i], beta);

    float xh[8] = {0.f, 0.f, 0.f, 0.f, 0.f, 0.f, 0.f, 0.f};
    float scale = 1.f;

#pragma unroll
    for (int m = 0; m < 3; m++) {
        // ---- encode layer m (R1-verbatim numerics) ----
        float t[8], cp[8];
#pragma unroll
        for (int i = 0; i < 8; i++) t[i] = xl[i] + eps[i];
        cp_e8<false>(t, cp);

        float z[8];
        z[0] = 0.5f * cp[0];
        float sum06 = z[0];
#pragma unroll
        for (int i = 1; i < 7; i++) { z[i] = cp[i] + z[i - 1]; sum06 += z[i]; }
        z[7] = 2.f * cp[7] - sum06;

        float b[8];
#pragma unroll
        for (int i = 0; i < 8; i++) {
            float q = truncf(z[i] * 0.25f);
            float r = __fmaf_rn(-4.f, q, z[i]);   // exact (dyadic)
            b[i] = cround(r);
        }
#pragma unroll
        for (int i = 0; i < 8; i++) xl[i] = cp[i] * 0.25f;

        // ---- decode layer m (R1-verbatim numerics) ----
        float h = 0.5f * b[7];
        float g[8];
        g[0] = 2.f * b[0] - b[1] + h;
#pragma unroll
        for (int j = 1; j < 6; j++) g[j] = b[j] - b[j + 1] + h;
        g[6] = b[6] + h;
        g[7] = h;

        float gq[8], cp2[8];
#pragma unroll
        for (int i = 0; i < 8; i++) gq[i] = g[i] * 0.25f;   // exact eighths
        cp_e8<true>(gq, cp2);

#pragma unroll
        for (int i = 0; i < 8; i++) {
            float xi = g[i] - 4.f * cp2[i];
            xh[i] += scale * xi;
        }
        scale *= 4.f;
    }

    float4 o0, o1;
    if (beta1) {
        o0.x = xh[0]; o0.y = xh[1]; o0.z = xh[2]; o0.w = xh[3];
        o1.x = xh[4]; o1.y = xh[5]; o1.z = xh[6]; o1.w = xh[7];
    } else {
        o0.x = beta * xh[0]; o0.y = beta * xh[1];
        o0.z = beta * xh[2]; o0.w = beta * xh[3];
        o1.x = beta * xh[4]; o1.y = beta * xh[5];
        o1.z = beta * xh[6]; o1.w = beta * xh[7];
    }
    outp[2 * row]     = o0;
    outp[2 * row + 1] = o1;
}

extern "C" void kernel_launch(void* const* d_in, const int* in_sizes, int n_in,
                              void* d_out, int out_size)
{
    const float* x = (const float*)d_in[0];
    const float* beta = nullptr;
    const float* eps  = nullptr;
    for (int i = 1; i < n_in; i++) {
        if (in_sizes[i] == 1) beta = (const float*)d_in[i];
        else if (in_sizes[i] == 8) eps = (const float*)d_in[i];
    }
    int nrows = in_sizes[0] / 8;
    int threads = 256;
    int blocks = (nrows + threads - 1) / threads;
    lq_kernel<<<blocks, threads>>>((const float4*)x, beta, eps, (float4*)d_out, nrows);
}

// round 10
// speedup vs baseline: 1.2899x; 1.0349x over previous
#include <cuda_runtime.h>

// LatticeQuantizer: hierarchical nested E8 lattice quantize (M=3, Q=4).
// PROVEN RULES (bisect rounds 1-9):
//  - xs = fl(x-0.5) is INEXACT for |x|<0.5 -> encode-B candidate must be
//    materialized from x in reference order. Decode inputs are exact
//    eighths -> residual forms / FMA / reordered exact sums bit-identical.
//  - A-branch residuals (x - cround(x)) are exact for ALL inputs.
//  - rk==0 implies all residuals zero and argmax k==0 -> tie step sign
//    precomputable from lane 0.
// NEW (this round, both exact-dyadic identities):
//  - decode: g - 4*cp_e8(g/4) == 4*(picked residual, flip lane -> rc);
//    no lattice point/xi materialization needed.
//  - layer hand-off: t = fma(cp, 0.25, eps) == fl(fl(cp*0.25) + eps).

#define TINY_F 1.1920928955078125e-07f  // np.finfo(float32).eps

static __device__ __forceinline__ float cround(float x) {
    float s = copysignf(TINY_F, x);
    return floorf((x - s) + 0.5f);
}

// ---- encode-path closest point (R9-verbatim numerics) ----
static __device__ __forceinline__ void cp_e8_enc(const float x[8], float out[8]) {
    float rA[8]; float sA = 0.f;
#pragma unroll
    for (int i = 0; i < 8; i++) {
        float f = cround(x[i]);
        rA[i] = x[i] - f;          // exact
        sA += f;                   // exact (small ints)
    }
    float rkA = rA[0]; int kA = 0;
#pragma unroll
    for (int i = 1; i < 8; i++) {
        bool gt = fabsf(rA[i]) > fabsf(rkA);   // FIRST max wins
        rkA = gt ? rA[i] : rkA;
        kA  = gt ? i     : kA;
    }
    float tieA  = (x[0] >= 0.f) ? -1.f : 1.f;
    float stepA = (rkA > 0.f) ? 1.f : ((rkA < 0.f) ? -1.f : tieA);
    bool oddA = (((int)sA) & 1) != 0;
    int  kAe  = oddA ? kA : 8;
    float rcA = rkA - stepA;

    float rB[8], fB[8]; float sB = 0.f;
#pragma unroll
    for (int i = 0; i < 8; i++) {
        float xs = x[i] - 0.5f;
        float f  = cround(xs);
        fB[i] = f;
        rB[i] = xs - f;
        sB += f;
    }
    float rkB = rB[0]; int kB = 0;
#pragma unroll
    for (int i = 1; i < 8; i++) {
        bool gt = fabsf(rB[i]) > fabsf(rkB);
        rkB = gt ? rB[i] : rkB;
        kB  = gt ? i     : kB;
    }
    float tieB  = ((x[0] - 0.5f) >= 0.f) ? -1.f : 1.f;
    float stepB = (rkB > 0.f) ? 1.f : ((rkB < 0.f) ? -1.f : tieB);
    bool oddB = (((int)sB) & 1) != 0;
    int  kBe  = oddB ? kB : 8;

    // encode: B materialized from fB in reference order; A residual form.
    float d0 = 0.f, d1 = 0.f;
    float yB[8];
#pragma unroll
    for (int i = 0; i < 8; i++) {
        float addB = (i == kBe) ? stepB : 0.f;
        yB[i] = (fB[i] + addB) + 0.5f;
        float a  = (i == kAe) ? rcA : rA[i];
        float rb = x[i] - yB[i];
        d0 = __fadd_rn(d0, __fmul_rn(a, a));
        d1 = __fadd_rn(d1, __fmul_rn(rb, rb));
    }
    bool p0 = d0 < d1;
#pragma unroll
    for (int i = 0; i < 8; i++) {
        float addA = (i == kAe) ? stepA : 0.f;
        float oA = (x[i] - rA[i]) + addA;      // fA exact, +-1 exact
        out[i] = p0 ? oA : yB[i];
    }
}

// ---- decode-path: returns v[i] = gq[i] - cp_e8(gq)[i] (exact residuals,
// flip lane -> rc). Caller uses xi = 4*v. All inputs exact eighths. ----
static __device__ __forceinline__ void cp_e8_dec_res(const float x[8], float v[8]) {
    float rA[8]; float sA = 0.f;
#pragma unroll
    for (int i = 0; i < 8; i++) {
        float f = cround(x[i]);
        rA[i] = x[i] - f;
        sA += f;
    }
    float rkA = rA[0]; int kA = 0;
#pragma unroll
    for (int i = 1; i < 8; i++) {
        bool gt = fabsf(rA[i]) > fabsf(rkA);
        rkA = gt ? rA[i] : rkA;
        kA  = gt ? i     : kA;
    }
    float tieA  = (x[0] >= 0.f) ? -1.f : 1.f;
    float stepA = (rkA > 0.f) ? 1.f : ((rkA < 0.f) ? -1.f : tieA);
    bool oddA = (((int)sA) & 1) != 0;
    int  kAe  = oddA ? kA : 8;
    float rcA = rkA - stepA;

    float rB[8]; float sB = 0.f;
#pragma unroll
    for (int i = 0; i < 8; i++) {
        float xs = x[i] - 0.5f;    // exact here (x on 1/8 grid)
        float f  = cround(xs);
        rB[i] = xs - f;
        sB += f;
    }
    float rkB = rB[0]; int kB = 0;
#pragma unroll
    for (int i = 1; i < 8; i++) {
        bool gt = fabsf(rB[i]) > fabsf(rkB);
        rkB = gt ? rB[i] : rkB;
        kB  = gt ? i     : kB;
    }
    float tieB  = ((x[0] - 0.5f) >= 0.f) ? -1.f : 1.f;
    float stepB = (rkB > 0.f) ? 1.f : ((rkB < 0.f) ? -1.f : tieB);
    bool oddB = (((int)sB) & 1) != 0;
    int  kBe  = oddB ? kB : 8;
    float rcB = rkB - stepB;

    // exact-domain distances: FMA sums + tie adjustment (bisect-proven)
    float d0 = 0.f, d1 = 0.f;
#pragma unroll
    for (int i = 0; i < 8; i++) {
        d0 = __fmaf_rn(rA[i], rA[i], d0);
        d1 = __fmaf_rn(rB[i], rB[i], d1);
    }
    float adjA = __fmul_rn(rcA, rcA) - __fmul_rn(rkA, rkA);  // exact
    float adjB = __fmul_rn(rcB, rcB) - __fmul_rn(rkB, rkB);
    d0 += oddA ? adjA : 0.f;
    d1 += oddB ? adjB : 0.f;
    bool p0 = d0 < d1;

    int   ksel = p0 ? kAe : kBe;
    float rcs  = p0 ? rcA : rcB;
#pragma unroll
    for (int i = 0; i < 8; i++) {
        float rs = p0 ? rA[i] : rB[i];
        v[i] = (i == ksel) ? rcs : rs;
    }
}

__global__ void __launch_bounds__(256)
lq_kernel(const float4* __restrict__ xin,
          const float* __restrict__ betap,
          const float* __restrict__ epsp,
          float4* __restrict__ outp,
          int nrows)
{
    int row = blockIdx.x * blockDim.x + threadIdx.x;
    if (row >= nrows) return;

    float beta = __ldg(betap);
    float eps[8];
#pragma unroll
    for (int i = 0; i < 8; i++) eps[i] = __ldg(epsp + i);

    float4 a0 = __ldg(xin + 2 * row);
    float4 a1 = __ldg(xin + 2 * row + 1);
    float x[8] = {a0.x, a0.y, a0.z, a0.w, a1.x, a1.y, a1.z, a1.w};

    bool beta1 = (beta == 1.0f);

    // layer-0 encode input: t = x/beta + eps (x/1.0 == x bitwise)
    float t[8];
#pragma unroll
    for (int i = 0; i < 8; i++) {
        float xl = beta1 ? x[i] : __fdiv_rn(x[i], beta);
        t[i] = xl + eps[i];
    }

    float xh[8] = {0.f, 0.f, 0.f, 0.f, 0.f, 0.f, 0.f, 0.f};

#pragma unroll
    for (int m = 0; m < 3; m++) {
        // ---- encode layer m ----
        float cp[8];
        cp_e8_enc(t, cp);

        // z = cp @ G_inv (analytic forward solve; exact quarter-integers)
        float z[8];
        z[0] = 0.5f * cp[0];
        float sum06 = z[0];
#pragma unroll
        for (int i = 1; i < 7; i++) { z[i] = cp[i] + z[i - 1]; sum06 += z[i]; }
        z[7] = 2.f * cp[7] - sum06;

        // b = custom_round(fmod(z,4)); fmod exact; cround REQUIRED
        float b[8];
#pragma unroll
        for (int i = 0; i < 8; i++) {
            float q = truncf(z[i] * 0.25f);
            float r = __fmaf_rn(-4.f, q, z[i]);   // exact (dyadic)
            b[i] = cround(r);
        }

        // next layer input: t = fma(cp, 1/Q, eps) == fl(fl(cp*0.25)+eps)
        if (m < 2) {
#pragma unroll
            for (int i = 0; i < 8; i++)
                t[i] = __fmaf_rn(cp[i], 0.25f, eps[i]);
        }

        // ---- decode layer m: xi = g - 4*cp_e8(g/4) == 4*v ----
        float h = 0.5f * b[7];
        float g[8];
        g[0] = 2.f * b[0] - b[1] + h;
#pragma unroll
        for (int j = 1; j < 6; j++) g[j] = b[j] - b[j + 1] + h;
        g[6] = b[6] + h;
        g[7] = h;

        float gq[8];
#pragma unroll
        for (int i = 0; i < 8; i++) gq[i] = g[i] * 0.25f;   // exact eighths
        float v[8];
        cp_e8_dec_res(gq, v);

        // xh += scale * xi = (4*scale) * v  — all exact dyadic
        float c4 = (m == 0) ? 4.f : ((m == 1) ? 16.f : 64.f);
#pragma unroll
        for (int i = 0; i < 8; i++)
            xh[i] = __fmaf_rn(c4, v[i], xh[i]);
    }

    float4 o0, o1;
    if (beta1) {
        o0.x = xh[0]; o0.y = xh[1]; o0.z = xh[2]; o0.w = xh[3];
        o1.x = xh[4]; o1.y = xh[5]; o1.z = xh[6]; o1.w = xh[7];
    } else {
        o0.x = beta * xh[0]; o0.y = beta * xh[1];
        o0.z = beta * xh[2]; o0.w = beta * xh[3];
        o1.x = beta * xh[4]; o1.y = beta * xh[5];
        o1.z = beta * xh[6]; o1.w = beta * xh[7];
    }
    outp[2 * row]     = o0;
    outp[2 * row + 1] = o1;
}

extern "C" void kernel_launch(void* const* d_in, const int* in_sizes, int n_in,
                              void* d_out, int out_size)
{
    const float* x = (const float*)d_in[0];
    const float* beta = nullptr;
    const float* eps  = nullptr;
    for (int i = 1; i < n_in; i++) {
        if (in_sizes[i] == 1) beta = (const float*)d_in[i];
        else if (in_sizes[i] == 8) eps = (const float*)d_in[i];
    }
    int nrows = in_sizes[0] / 8;
    int threads = 256;
    int blocks = (nrows + threads - 1) / threads;
    lq_kernel<<<blocks, threads>>>((const float4*)x, beta, eps, (float4*)d_out, nrows);
}